// round 5
// baseline (speedup 1.0000x reference)
#include <cuda_runtime.h>
#include <cuda_bf16.h>

static constexpr int N = 256;
static constexpr int B = 512;
static constexpr int M = N * (N - 1) / 2;  // 32640 (multiple of 4)
static constexpr int ILP = 4;              // independent batch rows per thread
static constexpr int TPB = 64;

__device__ __forceinline__ float sqrt_approx(float x) {
    float r;
    asm("sqrt.approx.f32 %0, %1;" : "=f"(r) : "f"(x));
    return r;
}

// One column step of the reference recurrence, reproducing its rounding:
//   t = 1 - rowsum ; x2 = (z*z) * t ; rowsum = rowsum + x2 ; out = sqrt(x2)*sign(z)
// __fadd_rn/__fmul_rn block FMA contraction so the fp32 sequence matches the
// reference's unfused mul/add (keeps the deep-column 1-rowsum plateau).
__device__ __forceinline__ float chol_step(float z, float& rowsum) {
    float t  = __fadd_rn(1.0f, -rowsum);
    float z2 = __fmul_rn(z, z);
    float x2 = __fmul_rn(z2, t);
    rowsum   = __fadd_rn(rowsum, x2);
    return copysignf(sqrt_approx(x2), z);
}

// OFS = (row base offset) & 3 — identical for all ILP streams since the
// stream stride M is a multiple of 4. Input read via 16B-aligned float4
// loads with a rolling funnel window; output via float4 stores (row base
// is 1KB-aligned).
template <int OFS>
__device__ __forceinline__ void do_rows(const float* __restrict__ zbase,
                                        float* __restrict__ obase, int i) {
    float rowsum[ILP];
    const float4* __restrict__ a4[ILP];
    float4* __restrict__ o4[ILP];
    float4 cur[ILP];

    #pragma unroll
    for (int s = 0; s < ILP; ++s) {
        rowsum[s] = 0.0f;
        a4[s] = reinterpret_cast<const float4*>(zbase + (size_t)s * M - OFS);
        o4[s] = reinterpret_cast<float4*>(obase + (size_t)s * N * N);
    }

    int j = 0;
    if (i >= 4) {
        #pragma unroll
        for (int s = 0; s < ILP; ++s) cur[s] = a4[s][0];
        int q = 1;
        for (; j + 4 <= i; j += 4, ++q) {
            const bool more = (j + 8 <= i);  // OFS==0: don't read past last needed quad
            #pragma unroll
            for (int s = 0; s < ILP; ++s) {
                float e0, e1, e2, e3;
                if (OFS == 0) {
                    e0 = cur[s].x; e1 = cur[s].y; e2 = cur[s].z; e3 = cur[s].w;
                    if (more) cur[s] = a4[s][q];
                } else {
                    float4 nxt = a4[s][q];
                    if (OFS == 1)      { e0 = cur[s].y; e1 = cur[s].z; e2 = cur[s].w; e3 = nxt.x; }
                    else if (OFS == 2) { e0 = cur[s].z; e1 = cur[s].w; e2 = nxt.x;    e3 = nxt.y; }
                    else               { e0 = cur[s].w; e1 = nxt.x;    e2 = nxt.y;    e3 = nxt.z; }
                    cur[s] = nxt;
                }
                float4 o;
                o.x = chol_step(e0, rowsum[s]);
                o.y = chol_step(e1, rowsum[s]);
                o.z = chol_step(e2, rowsum[s]);
                o.w = chol_step(e3, rowsum[s]);
                o4[s][j >> 2] = o;
            }
        }
    }

    // Boundary quad per stream: remaining scan elements (j..i-1), diagonal 1
    // at i, zeros after. Loads predicated so we never read past the buffer.
    #pragma unroll
    for (int s = 0; s < ILP; ++s) {
        const float* __restrict__ zrow = zbase + (size_t)s * M;
        float4 o;
        o.x = (j + 0 < i) ? chol_step(zrow[j + 0], rowsum[s])
                          : ((j + 0 == i) ? 1.0f : 0.0f);
        o.y = (j + 1 < i) ? chol_step(zrow[j + 1], rowsum[s])
                          : ((j + 1 == i) ? 1.0f : 0.0f);
        o.z = (j + 2 < i) ? chol_step(zrow[j + 2], rowsum[s])
                          : ((j + 2 == i) ? 1.0f : 0.0f);
        o.w = (j + 3 < i) ? chol_step(zrow[j + 3], rowsum[s])
                          : ((j + 3 == i) ? 1.0f : 0.0f);
        o4[s][j >> 2] = o;
    }

    // Zero-fill the strict upper triangle of each stream's row.
    for (int qq = (j >> 2) + 1; qq < N / 4; ++qq) {
        #pragma unroll
        for (int s = 0; s < ILP; ++s)
            o4[s][qq] = make_float4(0.0f, 0.0f, 0.0f, 0.0f);
    }
}

__global__ void __launch_bounds__(TPB)
chol_from_z_kernel(const float* __restrict__ vec, float* __restrict__ out) {
    // Longest rows first so the triangular load balances across waves.
    int i = (N - 1) - (int)blockIdx.x;
    int b = ((int)blockIdx.y * TPB + (int)threadIdx.x) * ILP;

    int tri = (i * (i - 1)) >> 1;  // start of row i in the packed vec
    const float* zbase = vec + (size_t)b * M + tri;
    float* obase = out + ((size_t)b * N + i) * (size_t)N;

    switch (tri & 3) {  // uniform across the block (same i)
        case 0:  do_rows<0>(zbase, obase, i); break;
        case 1:  do_rows<1>(zbase, obase, i); break;
        case 2:  do_rows<2>(zbase, obase, i); break;
        default: do_rows<3>(zbase, obase, i); break;
    }
}

extern "C" void kernel_launch(void* const* d_in, const int* in_sizes, int n_in,
                              void* d_out, int out_size) {
    const float* vec = (const float*)d_in[0];
    float* out = (float*)d_out;
    dim3 grid(N, B / (TPB * ILP));  // (256, 2)
    chol_from_z_kernel<<<grid, TPB>>>(vec, out);
}

// round 6
// speedup vs baseline: 2.0830x; 2.0830x over previous
#include <cuda_runtime.h>
#include <cuda_bf16.h>

static constexpr int N   = 256;
static constexpr int B   = 512;
static constexpr int M   = N * (N - 1) / 2;  // 32640
static constexpr int TPB = 128;              // threads per block = batches per block
static constexpr int TJ  = 32;               // columns per tile
static constexpr int PAD = 33;               // smem row stride (conflict-free)

__device__ __forceinline__ float sqrt_approx(float x) {
    float r;
    asm("sqrt.approx.f32 %0, %1;" : "=f"(r) : "f"(x));
    return r;
}

// One column step of the reference recurrence, reproducing its rounding:
//   t = 1 - rowsum ; x2 = (z*z) * t ; rowsum = rowsum + x2 ; out = sqrt(x2)*sign(z)
// __fadd_rn/__fmul_rn block FMA contraction so the fp32 sequence matches the
// reference's unfused mul/add (keeps the deep-column 1-rowsum plateau).
__device__ __forceinline__ float chol_step(float z, float& rowsum) {
    float t  = __fadd_rn(1.0f, -rowsum);
    float z2 = __fmul_rn(z, z);
    float x2 = __fmul_rn(z2, t);
    rowsum   = __fadd_rn(rowsum, x2);
    return copysignf(sqrt_approx(x2), z);
}

__global__ void __launch_bounds__(TPB)
chol_from_z_kernel(const float* __restrict__ vec, float* __restrict__ out) {
    __shared__ float s[TPB * PAD];

    const int i   = (N - 1) - (int)blockIdx.x;   // longest rows first
    const int b0  = (int)blockIdx.y * TPB;
    const int tid = (int)threadIdx.x;
    const int tri = (i * (i - 1)) >> 1;

    const float* __restrict__ vbase = vec + (size_t)b0 * M + tri;  // row i scan start, batch b0
    float* __restrict__ obase = out + ((size_t)b0 * N + i) * (size_t)N;  // out[b0][i][0]

    // Cooperative tile mapping: idx = tid + k*TPB -> bb = idx>>5 (batch within
    // block), jj = idx&31 (column within tile). A warp has one bb and
    // jj = lane -> fully coalesced 128B global accesses.
    const int twid = tid >> 5;   // bb = 4*k + twid for load/store phases
    const int lane = tid & 31;

    float rowsum = 0.0f;
    int j0 = 0;

    // ---- full scan tiles: columns [j0, j0+32) all strictly below diagonal ----
    for (; j0 + TJ <= i; j0 += TJ) {
        // Phase L: coalesced global -> smem
        #pragma unroll
        for (int k = 0; k < TJ; ++k) {
            int bb = 4 * k + twid;
            s[bb * PAD + lane] = vbase[(size_t)bb * M + j0 + lane];
        }
        __syncthreads();

        // Phase C: thread = batch, serial scan over 32 columns (smem reads are
        // independent of the chain -> hoisted into v[] for full MLP).
        float v[TJ];
        #pragma unroll
        for (int jj = 0; jj < TJ; ++jj) v[jj] = s[tid * PAD + jj];
        #pragma unroll
        for (int jj = 0; jj < TJ; ++jj) v[jj] = chol_step(v[jj], rowsum);
        #pragma unroll
        for (int jj = 0; jj < TJ; ++jj) s[tid * PAD + jj] = v[jj];
        __syncthreads();

        // Phase S: coalesced smem -> global
        #pragma unroll
        for (int k = 0; k < TJ; ++k) {
            int bb = 4 * k + twid;
            obase[(size_t)bb * N * N + j0 + lane] = s[bb * PAD + lane];
        }
        __syncthreads();
    }

    // ---- mixed tile: contains the last scan columns, the diagonal, first zeros ----
    {
        #pragma unroll
        for (int k = 0; k < TJ; ++k) {
            int bb = 4 * k + twid;
            if (j0 + lane < i)
                s[bb * PAD + lane] = vbase[(size_t)bb * M + j0 + lane];
        }
        __syncthreads();

        #pragma unroll
        for (int jj = 0; jj < TJ; ++jj) {
            int j = j0 + jj;            // uniform across block (same i)
            float val;
            if (j < i)       val = chol_step(s[tid * PAD + jj], rowsum);
            else if (j == i) val = 1.0f;
            else             val = 0.0f;
            s[tid * PAD + jj] = val;
        }
        __syncthreads();

        #pragma unroll
        for (int k = 0; k < TJ; ++k) {
            int bb = 4 * k + twid;
            obase[(size_t)bb * N * N + j0 + lane] = s[bb * PAD + lane];
        }
    }

    // ---- pure-zero region: columns [j0+32, N), coalesced float4 stores ----
    {
        const int zstart = j0 + TJ;          // multiple of 32 -> 128B aligned
        const int nzq = (N - zstart) >> 2;   // float4 quads per batch row
        const float4 z4 = make_float4(0.0f, 0.0f, 0.0f, 0.0f);
        for (int bb = twid; bb < TPB; bb += 4) {
            float4* __restrict__ o4 =
                reinterpret_cast<float4*>(obase + (size_t)bb * N * N + zstart);
            for (int q = lane; q < nzq; q += 32)
                o4[q] = z4;
        }
    }
}

extern "C" void kernel_launch(void* const* d_in, const int* in_sizes, int n_in,
                              void* d_out, int out_size) {
    const float* vec = (const float*)d_in[0];
    float* out = (float*)d_out;
    dim3 grid(N, B / TPB);  // (256, 4) -> 1024 blocks, fully co-resident
    chol_from_z_kernel<<<grid, TPB>>>(vec, out);
}

// round 7
// speedup vs baseline: 2.1660x; 1.0398x over previous
#include <cuda_runtime.h>
#include <cuda_bf16.h>

static constexpr int N   = 256;
static constexpr int B   = 512;
static constexpr int M   = N * (N - 1) / 2;  // 32640
static constexpr int TPB = 64;               // threads = batches per block
static constexpr int PAD = 33;               // smem row stride (conflict-free)
static constexpr int NN  = N * N;

__device__ __forceinline__ float sqrt_approx(float x) {
    float r;
    asm("sqrt.approx.f32 %0, %1;" : "=f"(r) : "f"(x));
    return r;
}

// One column step of the reference recurrence, reproducing its rounding:
//   t = 1 - rowsum ; x2 = (z*z) * t ; rowsum = rowsum + x2 ; out = sqrt(x2)*sign(z)
// __fadd_rn/__fmul_rn block FMA contraction so the fp32 sequence matches the
// reference's unfused mul/add (keeps the deep-column 1-rowsum plateau).
__device__ __forceinline__ float chol_step(float z, float& rowsum) {
    float t  = __fadd_rn(1.0f, -rowsum);
    float z2 = __fmul_rn(z, z);
    float x2 = __fmul_rn(z2, t);
    rowsum   = __fadd_rn(rowsum, x2);
    return copysignf(sqrt_approx(x2), z);
}

// Process one output row i for 64 batches, software-pipelined over 32-column
// tiles with double-buffered smem. sA/sB are TPB*PAD floats each.
__device__ __forceinline__ void process_row(
    int i, const float* __restrict__ vrow, float* __restrict__ orow,
    float* __restrict__ sA, float* __restrict__ sB,
    int tid, int wrp, int lane)
{
    const int ntiles = (i >> 5) + 1;   // tiles 0..ntiles-1; last one is mixed
    float rowsum = 0.0f;
    float r[32];                       // prefetch registers (one tile, this warp's half)

    // ---- prologue: load tile 0 (predicated at the scan end) and stage it ----
    #pragma unroll
    for (int k = 0; k < 32; ++k) {
        int bb = 2 * k + wrp;          // batch within block
        int j  = lane;                 // column within tile 0
        r[k] = (j < i) ? vrow[(size_t)bb * M + j] : 0.0f;
    }
    float* cur = sA;
    float* nxt = sB;
    #pragma unroll
    for (int k = 0; k < 32; ++k) {
        int bb = 2 * k + wrp;
        cur[bb * PAD + lane] = r[k];
    }
    __syncthreads();

    for (int t = 0; t < ntiles; ++t) {
        const int j0 = t << 5;
        const bool full = (t + 1 < ntiles);

        // ---- prefetch tile t+1 into registers (overlaps with compute) ----
        if (full) {
            const int j1 = j0 + 32;
            #pragma unroll
            for (int k = 0; k < 32; ++k) {
                int bb = 2 * k + wrp;
                int j  = j1 + lane;
                r[k] = (j < i) ? vrow[(size_t)bb * M + j] : 0.0f;
            }
        }

        // ---- compute: thread = batch, serial chain over 32 columns ----
        if (full) {
            float v[32];
            #pragma unroll
            for (int jj = 0; jj < 32; ++jj) v[jj] = cur[tid * PAD + jj];
            #pragma unroll
            for (int jj = 0; jj < 32; ++jj) v[jj] = chol_step(v[jj], rowsum);
            #pragma unroll
            for (int jj = 0; jj < 32; ++jj) cur[tid * PAD + jj] = v[jj];
        } else {
            // mixed tile: last scan columns, diagonal 1 at i, zeros after
            #pragma unroll
            for (int jj = 0; jj < 32; ++jj) {
                int j = j0 + jj;       // uniform across block (same i)
                float val;
                if (j < i)       val = chol_step(cur[tid * PAD + jj], rowsum);
                else if (j == i) val = 1.0f;
                else             val = 0.0f;
                cur[tid * PAD + jj] = val;
            }
        }
        __syncthreads();

        // ---- store tile t (coalesced), stage tile t+1 into other buffer ----
        #pragma unroll
        for (int k = 0; k < 32; ++k) {
            int bb = 2 * k + wrp;
            orow[(size_t)bb * NN + j0 + lane] = cur[bb * PAD + lane];
        }
        if (full) {
            #pragma unroll
            for (int k = 0; k < 32; ++k) {
                int bb = 2 * k + wrp;
                nxt[bb * PAD + lane] = r[k];
            }
        }
        __syncthreads();
        float* tmp = cur; cur = nxt; nxt = tmp;
    }

    // ---- pure-zero region: columns [ntiles*32, N), coalesced float4 stores ----
    const int zstart = ntiles << 5;    // multiple of 32 -> 128B aligned
    const int nzq = (N - zstart) >> 2;
    if (nzq > 0) {
        const float4 z4 = make_float4(0.0f, 0.0f, 0.0f, 0.0f);
        for (int bb = wrp; bb < TPB; bb += 2) {
            float4* __restrict__ o4 =
                reinterpret_cast<float4*>(orow + (size_t)bb * NN + zstart);
            for (int q = lane; q < nzq; q += 32)
                o4[q] = z4;
        }
    }
}

__global__ void __launch_bounds__(TPB)
chol_from_z_kernel(const float* __restrict__ vec, float* __restrict__ out) {
    __shared__ float sA[TPB * PAD];
    __shared__ float sB[TPB * PAD];

    // Row pairing (i, N-1-i): every block does exactly N-1 = 255 scan elements
    // per thread -> perfectly uniform block runtimes across the grid.
    const int i1  = (N - 1) - (int)blockIdx.x;   // 128..255 (long row first)
    const int i2  = (int)blockIdx.x;             // 0..127
    const int b0  = (int)blockIdx.y * TPB;
    const int tid = (int)threadIdx.x;
    const int wrp = tid >> 5;
    const int lane = tid & 31;

    {
        const int tri = (i1 * (i1 - 1)) >> 1;
        process_row(i1, vec + (size_t)b0 * M + tri,
                    out + ((size_t)b0 * N + i1) * (size_t)N,
                    sA, sB, tid, wrp, lane);
    }
    __syncthreads();
    {
        const int tri = (i2 * (i2 - 1)) >> 1;
        process_row(i2, vec + (size_t)b0 * M + tri,
                    out + ((size_t)b0 * N + i2) * (size_t)N,
                    sA, sB, tid, wrp, lane);
    }
}

extern "C" void kernel_launch(void* const* d_in, const int* in_sizes, int n_in,
                              void* d_out, int out_size) {
    const float* vec = (const float*)d_in[0];
    float* out = (float*)d_out;
    dim3 grid(N / 2, B / TPB);  // (128, 8) -> 1024 uniform blocks
    chol_from_z_kernel<<<grid, TPB>>>(vec, out);
}